// round 1
// baseline (speedup 1.0000x reference)
#include <cuda_runtime.h>
#include <cstdint>

#define BATCH 8
#define SEQ   2048
#define DIM   64
#define PAIR_BASE 20000
#define BM_WORDS  12500000   // 20000*20000 bits / 32 = 50 MB

// ---------------- device scratch (static globals: allocation-free) ----------
__device__ unsigned int g_bitmap[BM_WORDS];          // zero-init at load; idempotent atomicOr build
__device__ float g_uc[BATCH][SEQ][DIM];              // compacted tf rows of u
__device__ float g_vc[BATCH][SEQ][DIM];              // compacted active cols of v
__device__ int   g_row_id[BATCH][SEQ];
__device__ int   g_col_id[BATCH][SEQ];
__device__ int   g_nrows[BATCH];
__device__ int   g_ncols[BATCH];
__device__ double g_numer;

// ---------------- init ------------------------------------------------------
__global__ void init_kernel() {
    int t = threadIdx.x;
    if (t < BATCH) { g_nrows[t] = 0; g_ncols[t] = 0; }
    if (t == 0)    g_numer = 0.0;
}

// ---------------- bitmap build (idempotent across replays) ------------------
__global__ void bitmap_kernel(const int* __restrict__ keys, int M) {
    int i = blockIdx.x * blockDim.x + threadIdx.x;
    if (i < M) {
        unsigned int k = (unsigned int)keys[i];
        atomicOr(&g_bitmap[k >> 5], 1u << (k & 31));
    }
}

// ---------------- compaction: gather tf rows / active cols ------------------
__global__ void compact_kernel(const int* __restrict__ ids,
                               const unsigned char* __restrict__ tf,
                               const unsigned char* __restrict__ act,
                               const float* __restrict__ u,
                               const float* __restrict__ v) {
    // 64 blocks x 256 threads: block handles batch b = blockIdx.x>>3, 256-elem chunk
    int b = blockIdx.x >> 3;
    int s = ((blockIdx.x & 7) << 8) + threadIdx.x;
    int gs = b * SEQ + s;
    int id = ids[gs];
    if (tf[gs]) {
        int i = atomicAdd(&g_nrows[b], 1);
        g_row_id[b][i] = id;
        const float4* src = (const float4*)(u + (size_t)gs * DIM);
        float4* dst = (float4*)(&g_uc[b][i][0]);
        #pragma unroll
        for (int q = 0; q < 16; q++) dst[q] = src[q];
    }
    if (act[gs]) {
        int i = atomicAdd(&g_ncols[b], 1);
        g_col_id[b][i] = id;
        const float4* src = (const float4*)(v + (size_t)gs * DIM);
        float4* dst = (float4*)(&g_vc[b][i][0]);
        #pragma unroll
        for (int q = 0; q < 16; q++) dst[q] = src[q];
    }
}

// ---------------- main: tiled GEMM + fused BCE epilogue ---------------------
// 128x128 tile per block, 256 threads, 8x8 microtile, K staged in 2x32.
__global__ __launch_bounds__(256, 2)
void main_kernel() {
    __shared__ float sU[128][33];   // [row][k] padded: conflict-free
    __shared__ float sV[128][33];   // [col][k]
    __shared__ int sRid[128];
    __shared__ int sCid[128];

    const int b   = blockIdx.z;
    const int nr  = g_nrows[b];
    const int nc  = g_ncols[b];
    const int row0 = blockIdx.y * 128;
    const int col0 = blockIdx.x * 128;
    if (row0 >= nr || col0 >= nc) return;

    const int tid = threadIdx.x;
    const int tx  = tid & 15;
    const int ty  = tid >> 4;

    if (tid < 128) {
        int r = row0 + tid;
        sRid[tid] = (r < nr) ? g_row_id[b][r] : 0;
    } else {
        int c = col0 + (tid - 128);
        sCid[tid - 128] = (c < nc) ? g_col_id[b][c] : 0;
    }

    float acc[8][8];
    #pragma unroll
    for (int i = 0; i < 8; i++)
        #pragma unroll
        for (int j = 0; j < 8; j++) acc[i][j] = 0.f;

    #pragma unroll
    for (int ks = 0; ks < 2; ks++) {
        const int k0 = ks * 32;
        // load stage: 128 rows x 32 k. thread -> (row = tid>>1, k-half = (tid&1)*16)
        {
            const int r  = tid >> 1;
            const int kh = (tid & 1) << 4;
            // row0+r < 2048 always (row0 <= 1920): in-bounds reads; stale data masked later
            const float4* su = (const float4*)(&g_uc[b][row0 + r][k0 + kh]);
            const float4* sv = (const float4*)(&g_vc[b][col0 + r][k0 + kh]);
            #pragma unroll
            for (int q = 0; q < 4; q++) {
                float4 a = su[q];
                sU[r][kh + 4*q + 0] = a.x; sU[r][kh + 4*q + 1] = a.y;
                sU[r][kh + 4*q + 2] = a.z; sU[r][kh + 4*q + 3] = a.w;
                float4 c = sv[q];
                sV[r][kh + 4*q + 0] = c.x; sV[r][kh + 4*q + 1] = c.y;
                sV[r][kh + 4*q + 2] = c.z; sV[r][kh + 4*q + 3] = c.w;
            }
        }
        __syncthreads();

        #pragma unroll 8
        for (int k = 0; k < 32; k++) {
            float a[8], bb[8];
            #pragma unroll
            for (int i = 0; i < 8; i++) a[i] = sU[ty + 16*i][k];
            #pragma unroll
            for (int j = 0; j < 8; j++) bb[j] = sV[tx + 16*j][k];
            #pragma unroll
            for (int i = 0; i < 8; i++)
                #pragma unroll
                for (int j = 0; j < 8; j++)
                    acc[i][j] = fmaf(a[i], bb[j], acc[i][j]);
        }
        __syncthreads();
    }

    // ---- fused epilogue: clamp, prior-set bit test, -log, reduce ----
    float lsum = 0.f;
    #pragma unroll
    for (int i = 0; i < 8; i++) {
        const int lr = ty + 16*i;
        const int r  = row0 + lr;
        if (r >= nr) continue;
        const int rid = sRid[lr] * PAIR_BASE;
        #pragma unroll
        for (int j = 0; j < 8; j++) {
            const int lc = tx + 16*j;
            const int c  = col0 + lc;
            if (c >= nc) continue;
            float p = acc[i][j];
            p = fminf(fmaxf(p, 1e-8f), 1.0f);
            const unsigned int key = (unsigned int)(rid + sCid[lc]);
            const unsigned int w = g_bitmap[key >> 5];
            const bool pos = (w >> (key & 31)) & 1u;
            const float x = pos ? p : (1.0f - p);
            lsum -= __logf(x);
        }
    }
    // warp reduce + per-warp atomic
    #pragma unroll
    for (int o = 16; o; o >>= 1) lsum += __shfl_xor_sync(0xffffffffu, lsum, o);
    if ((tid & 31) == 0) atomicAdd(&g_numer, (double)lsum);
}

// ---------------- finalize ---------------------------------------------------
__global__ void finalize_kernel(float* __restrict__ out, int n) {
    double denom = 0.0;
    #pragma unroll
    for (int b = 0; b < BATCH; b++)
        denom += (double)g_nrows[b] * (double)g_ncols[b];
    float r = (float)(g_numer / (denom + 1e-8));
    for (int i = threadIdx.x; i < n; i += blockDim.x) out[i] = r;
}

// ---------------- launch ------------------------------------------------------
extern "C" void kernel_launch(void* const* d_in, const int* in_sizes, int n_in,
                              void* d_out, int out_size) {
    const int*           ids  = (const int*)d_in[0];
    const unsigned char* tf   = (const unsigned char*)d_in[1];
    const unsigned char* act  = (const unsigned char*)d_in[2];
    const int*           keys = (const int*)d_in[3];
    const float*         u    = (const float*)d_in[4];
    const float*         v    = (const float*)d_in[5];
    const int M = in_sizes[3];

    init_kernel<<<1, 32>>>();
    bitmap_kernel<<<(M + 255) / 256, 256>>>(keys, M);
    compact_kernel<<<64, 256>>>(ids, tf, act, u, v);
    dim3 grid(SEQ / 128, SEQ / 128, BATCH);
    main_kernel<<<grid, 256>>>();
    finalize_kernel<<<1, 256>>>((float*)d_out, out_size);
}

// round 3
// speedup vs baseline: 1.0580x; 1.0580x over previous
#include <cuda_runtime.h>
#include <cstdint>

#define BATCH 8
#define SEQ   2048
#define DIM   64
#define PAIR_BASE 20000
#define BM_WORDS  12500000   // 20000*20000 bits / 32 = 50 MB

// ---------------- device scratch (static globals: allocation-free) ----------
__device__ unsigned int g_bitmap[BM_WORDS];   // zero at load; idempotent atomicOr build
__device__ float  g_uc[BATCH][SEQ][DIM];      // compacted tf rows of u
__device__ float  g_vc[BATCH][SEQ][DIM];      // compacted active cols of v
__device__ int    g_row_id[BATCH][SEQ];
__device__ int    g_col_id[BATCH][SEQ];
__device__ int    g_nrows[BATCH];             // zero at load; re-zeroed by finalize
__device__ int    g_ncols[BATCH];
__device__ double g_numer;                    // zero at load; re-zeroed by finalize

// ---------------- packed fp32x2 helpers (Blackwell FFMA2) --------------------
typedef unsigned long long u64;
__device__ __forceinline__ u64 splat2(float x) {
    u64 d; asm("mov.b64 %0, {%1, %1};" : "=l"(d) : "f"(x)); return d;
}
__device__ __forceinline__ void ffma2(u64& d, u64 a, u64 b) {
    asm("fma.rn.f32x2 %0, %1, %2, %0;" : "+l"(d) : "l"(a), "l"(b));
}
__device__ __forceinline__ void unpack2(float& lo, float& hi, u64 v) {
    asm("mov.b64 {%0, %1}, %2;" : "=f"(lo), "=f"(hi) : "l"(v));
}

// ---------------- prep: bitmap build + compaction (fused) --------------------
__global__ void prep_kernel(const int* __restrict__ ids,
                            const unsigned char* __restrict__ tf,
                            const unsigned char* __restrict__ act,
                            const float* __restrict__ u,
                            const float* __restrict__ v,
                            const int* __restrict__ keys, int M, int nbm) {
    int bid = blockIdx.x;
    if (bid < nbm) {
        int i = bid * 256 + threadIdx.x;
        if (i < M) {
            unsigned int k = (unsigned int)keys[i];
            atomicOr(&g_bitmap[k >> 5], 1u << (k & 31));
        }
        return;
    }
    // compaction blocks: 64 of them (8 per batch)
    int cb = bid - nbm;
    int b  = cb >> 3;
    int s  = ((cb & 7) << 8) + threadIdx.x;
    int gs = b * SEQ + s;
    int id = ids[gs];
    if (tf[gs]) {
        int i = atomicAdd(&g_nrows[b], 1);
        g_row_id[b][i] = id;
        const float4* src = (const float4*)(u + (size_t)gs * DIM);
        float4* dst = (float4*)(&g_uc[b][i][0]);
        #pragma unroll
        for (int q = 0; q < 16; q++) dst[q] = src[q];
    }
    if (act[gs]) {
        int i = atomicAdd(&g_ncols[b], 1);
        g_col_id[b][i] = id;
        const float4* src = (const float4*)(v + (size_t)gs * DIM);
        float4* dst = (float4*)(&g_vc[b][i][0]);
        #pragma unroll
        for (int q = 0; q < 16; q++) dst[q] = src[q];
    }
}

// ---------------- main: 128x128 tile GEMM (FFMA2) + fused BCE epilogue ------
// 256 threads, microtile 8 rows x 4 col-pairs per thread, K staged 2x32.
// Thread map: tx = tid&15, ty = tid>>4. rows r = ty+16i; cols c = 2tx+32p+e.
__global__ __launch_bounds__(256, 2)
void main_kernel() {
    __shared__ __align__(16) float sU[128][33];    // [row][k], padded
    __shared__ __align__(16) float sVt[32][130];   // [k][col], col-pairs contiguous
    __shared__ int sRid[128];
    __shared__ int sCid[128];

    const int b    = blockIdx.z;
    const int nr   = g_nrows[b];
    const int nc   = g_ncols[b];
    const int row0 = blockIdx.y * 128;
    const int col0 = blockIdx.x * 128;
    if (row0 >= nr || col0 >= nc) return;

    const int tid = threadIdx.x;
    const int tx  = tid & 15;
    const int ty  = tid >> 4;

    if (tid < 128) sRid[tid]       = g_row_id[b][row0 + tid];
    else           sCid[tid - 128] = g_col_id[b][col0 + tid - 128];

    u64 acc[8][4];
    #pragma unroll
    for (int i = 0; i < 8; i++)
        #pragma unroll
        for (int p = 0; p < 4; p++) acc[i][p] = 0ull;

    #pragma unroll
    for (int ks = 0; ks < 2; ks++) {
        const int k0 = ks * 32;
        // stage: thread -> (local index rr = tid>>1, k-half kh = (tid&1)*16)
        {
            const int rr = tid >> 1;
            const int kh = (tid & 1) << 4;
            const float4* su = (const float4*)(&g_uc[b][row0 + rr][k0 + kh]);
            const float4* sv = (const float4*)(&g_vc[b][col0 + rr][k0 + kh]);
            #pragma unroll
            for (int q = 0; q < 4; q++) {
                float4 a = su[q];
                sU[rr][kh + 4*q + 0] = a.x; sU[rr][kh + 4*q + 1] = a.y;
                sU[rr][kh + 4*q + 2] = a.z; sU[rr][kh + 4*q + 3] = a.w;
                float4 c = sv[q];
                sVt[kh + 4*q + 0][rr] = c.x; sVt[kh + 4*q + 1][rr] = c.y;
                sVt[kh + 4*q + 2][rr] = c.z; sVt[kh + 4*q + 3][rr] = c.w;
            }
        }
        __syncthreads();

        #pragma unroll 8
        for (int k = 0; k < 32; k++) {
            u64 bv[4];
            #pragma unroll
            for (int p = 0; p < 4; p++)
                bv[p] = *(const u64*)(&sVt[k][2*tx + 32*p]);
            #pragma unroll
            for (int i = 0; i < 8; i++) {
                u64 as = splat2(sU[ty + 16*i][k]);
                #pragma unroll
                for (int p = 0; p < 4; p++)
                    ffma2(acc[i][p], as, bv[p]);
            }
        }
        __syncthreads();
    }

    // ---- fused epilogue: clamp, prior bit test, -log, reduce ----
    float lsum = 0.f;
    #pragma unroll
    for (int i = 0; i < 8; i++) {
        const int lr = ty + 16*i;
        const int r  = row0 + lr;
        if (r >= nr) continue;
        const unsigned rbase = (unsigned)sRid[lr] * PAIR_BASE;
        #pragma unroll
        for (int p = 0; p < 4; p++) {
            float lo, hi;
            unpack2(lo, hi, acc[i][p]);
            #pragma unroll
            for (int e = 0; e < 2; e++) {
                const int lc = 2*tx + 32*p + e;
                const int c  = col0 + lc;
                if (c >= nc) continue;
                float pr = e ? hi : lo;
                pr = fminf(fmaxf(pr, 1e-8f), 1.0f);
                const unsigned key = rbase + (unsigned)sCid[lc];
                const unsigned w   = g_bitmap[key >> 5];
                const float x = ((w >> (key & 31)) & 1u) ? pr : (1.0f - pr);
                lsum -= __logf(x);
            }
        }
    }
    #pragma unroll
    for (int o = 16; o; o >>= 1) lsum += __shfl_xor_sync(0xffffffffu, lsum, o);
    if ((tid & 31) == 0) atomicAdd(&g_numer, (double)lsum);
}

// ---------------- finalize: result + re-zero state for next replay ----------
__global__ void finalize_kernel(float* __restrict__ out, int n) {
    __shared__ double s_res;
    if (threadIdx.x == 0) {
        double denom = 0.0;
        #pragma unroll
        for (int b = 0; b < BATCH; b++)
            denom += (double)g_nrows[b] * (double)g_ncols[b];
        s_res = g_numer / (denom + 1e-8);
        g_numer = 0.0;
        #pragma unroll
        for (int b = 0; b < BATCH; b++) { g_nrows[b] = 0; g_ncols[b] = 0; }
    }
    __syncthreads();
    float r = (float)s_res;
    for (int i = threadIdx.x; i < n; i += blockDim.x) out[i] = r;
}

// ---------------- launch ------------------------------------------------------
extern "C" void kernel_launch(void* const* d_in, const int* in_sizes, int n_in,
                              void* d_out, int out_size) {
    const int*           ids  = (const int*)d_in[0];
    const unsigned char* tf   = (const unsigned char*)d_in[1];
    const unsigned char* act  = (const unsigned char*)d_in[2];
    const int*           keys = (const int*)d_in[3];
    const float*         u    = (const float*)d_in[4];
    const float*         v    = (const float*)d_in[5];
    const int M   = in_sizes[3];
    const int nbm = (M + 255) / 256;

    prep_kernel<<<nbm + 64, 256>>>(ids, tf, act, u, v, keys, M, nbm);
    dim3 grid(SEQ / 128, SEQ / 128, BATCH);
    main_kernel<<<grid, 256>>>();
    finalize_kernel<<<1, 256>>>((float*)d_out, out_size);
}